// round 2
// baseline (speedup 1.0000x reference)
#include <cuda_runtime.h>
#include <math.h>

// Problem constants
#define PB 8          // batch
#define PN 128        // nodes
#define PD 256        // message size
#define PLH 512       // link hidden
#define PC 117        // classes
#define M_EDGE (PB*PN*PN)   // 131072 edge rows

// ---------------- scratch (static device globals; no allocation) ----------------
__device__ float g_ef[(size_t)M_EDGE * PD];      // resized edge features [b,i,w,d]
__device__ float g_es[(size_t)M_EDGE * PD];      // hidden edge state (transposed M)
__device__ float g_x1[(size_t)M_EDGE * PLH];     // link fn layer1 out
__device__ float g_h[PB * PN * PD];              // node hidden
__device__ float g_sig[M_EDGE];                  // sigmoid(adj)
__device__ float g_msum[PB * PN * PD];           // aggregated messages
__device__ float g_gi[PB * PN * 3 * PD];         // GRU input gates
__device__ float g_gh[PB * PN * 3 * PD];         // GRU hidden gates

__device__ __forceinline__ float sigmoidf(float x) { return 1.f / (1.f + __expf(-x)); }

// ---------------- generic TN SGEMM: C[M,N] = act(A[M,K] @ B[N,K]^T + bias[N]) ----------------
// 128x128 block tile, BK=16, 256 threads, 8x8 per-thread microtile.
__global__ __launch_bounds__(256, 2)
void sgemm_tn(const float* __restrict__ A, const float* __restrict__ B,
              const float* __restrict__ bias, float* __restrict__ C,
              int M, int N, int K, int relu)
{
    __shared__ float As[16][132];
    __shared__ float Bs[16][132];
    const int tid = threadIdx.x;
    const int m0 = blockIdx.y * 128;
    const int n0 = blockIdx.x * 128;
    const int lr = tid >> 2;          // 0..63
    const int lk = (tid & 3) * 4;     // 0,4,8,12
    const int tx = tid & 15;
    const int ty = tid >> 4;

    float acc[8][8];
#pragma unroll
    for (int i = 0; i < 8; i++)
#pragma unroll
        for (int j = 0; j < 8; j++) acc[i][j] = 0.f;

    for (int kt = 0; kt < K; kt += 16) {
        const bool fullk = (kt + 16 <= K);
#pragma unroll
        for (int half = 0; half < 2; half++) {
            const int row = lr + half * 64;
            // A tile
            {
                const int gm = m0 + row;
                float4 v = make_float4(0.f, 0.f, 0.f, 0.f);
                if (gm < M) {
                    const float* p = A + (size_t)gm * K + kt + lk;
                    if (fullk) v = *(const float4*)p;
                    else {
                        if (kt + lk + 0 < K) v.x = p[0];
                        if (kt + lk + 1 < K) v.y = p[1];
                        if (kt + lk + 2 < K) v.z = p[2];
                        if (kt + lk + 3 < K) v.w = p[3];
                    }
                }
                As[lk + 0][row] = v.x; As[lk + 1][row] = v.y;
                As[lk + 2][row] = v.z; As[lk + 3][row] = v.w;
            }
            // B tile
            {
                const int gn = n0 + row;
                float4 v = make_float4(0.f, 0.f, 0.f, 0.f);
                if (gn < N) {
                    const float* p = B + (size_t)gn * K + kt + lk;
                    if (fullk) v = *(const float4*)p;
                    else {
                        if (kt + lk + 0 < K) v.x = p[0];
                        if (kt + lk + 1 < K) v.y = p[1];
                        if (kt + lk + 2 < K) v.z = p[2];
                        if (kt + lk + 3 < K) v.w = p[3];
                    }
                }
                Bs[lk + 0][row] = v.x; Bs[lk + 1][row] = v.y;
                Bs[lk + 2][row] = v.z; Bs[lk + 3][row] = v.w;
            }
        }
        __syncthreads();
#pragma unroll
        for (int k = 0; k < 16; k++) {
            float4 a0 = *(const float4*)&As[k][ty * 4];
            float4 a1 = *(const float4*)&As[k][64 + ty * 4];
            float4 b0 = *(const float4*)&Bs[k][tx * 4];
            float4 b1 = *(const float4*)&Bs[k][64 + tx * 4];
            float a[8] = {a0.x, a0.y, a0.z, a0.w, a1.x, a1.y, a1.z, a1.w};
            float b[8] = {b0.x, b0.y, b0.z, b0.w, b1.x, b1.y, b1.z, b1.w};
#pragma unroll
            for (int i = 0; i < 8; i++)
#pragma unroll
                for (int j = 0; j < 8; j++)
                    acc[i][j] = fmaf(a[i], b[j], acc[i][j]);
        }
        __syncthreads();
    }

#pragma unroll
    for (int i = 0; i < 8; i++) {
        const int gm = m0 + ((i < 4) ? (ty * 4 + i) : (64 + ty * 4 + i - 4));
        if (gm >= M) continue;
#pragma unroll
        for (int j = 0; j < 8; j++) {
            const int gn = n0 + ((j < 4) ? (tx * 4 + j) : (64 + tx * 4 + j - 4));
            if (gn >= N) continue;
            float v = acc[i][j] + bias[gn];
            if (relu) v = fmaxf(v, 0.f);
            C[(size_t)gm * N + gn] = v;
        }
    }
}

// ---------------- fused link layer2+layer3 ----------------
// adj[m] = sum_n relu(x1[m,:] @ Wl2[n,:] + bl2[n]) * Wl3[n] + bl3; sig = sigmoid(adj)
// Block: 128 rows; inner loop over 4 column tiles of 128 (N=512), K=512.
__global__ __launch_bounds__(256, 2)
void link23_kernel(const float* __restrict__ x1, const float* __restrict__ Wl2,
                   const float* __restrict__ bl2, const float* __restrict__ Wl3,
                   const float* __restrict__ bl3,
                   float* __restrict__ adj, float* __restrict__ sig)
{
    __shared__ float As[16][132];
    __shared__ float Bs[16][132];
    __shared__ float wl3s[PLH];
    __shared__ float bl2s[PLH];
    const int tid = threadIdx.x;
    const int m0 = blockIdx.x * 128;
    const int lr = tid >> 2;
    const int lk = (tid & 3) * 4;
    const int tx = tid & 15;
    const int ty = tid >> 4;

    if (tid < PLH / 2) {           // 256 threads load 512 floats each array
        wl3s[tid] = Wl3[tid];           wl3s[tid + 256] = Wl3[tid + 256];
        bl2s[tid] = bl2[tid];           bl2s[tid + 256] = bl2[tid + 256];
    }
    __syncthreads();

    float padj[8];
#pragma unroll
    for (int i = 0; i < 8; i++) padj[i] = 0.f;

    for (int nt = 0; nt < 4; nt++) {
        const int n0 = nt * 128;
        float acc[8][8];
#pragma unroll
        for (int i = 0; i < 8; i++)
#pragma unroll
            for (int j = 0; j < 8; j++) acc[i][j] = 0.f;

        for (int kt = 0; kt < PLH; kt += 16) {
#pragma unroll
            for (int half = 0; half < 2; half++) {
                const int row = lr + half * 64;
                {
                    float4 v = *(const float4*)(x1 + (size_t)(m0 + row) * PLH + kt + lk);
                    As[lk + 0][row] = v.x; As[lk + 1][row] = v.y;
                    As[lk + 2][row] = v.z; As[lk + 3][row] = v.w;
                }
                {
                    float4 v = *(const float4*)(Wl2 + (size_t)(n0 + row) * PLH + kt + lk);
                    Bs[lk + 0][row] = v.x; Bs[lk + 1][row] = v.y;
                    Bs[lk + 2][row] = v.z; Bs[lk + 3][row] = v.w;
                }
            }
            __syncthreads();
#pragma unroll
            for (int k = 0; k < 16; k++) {
                float4 a0 = *(const float4*)&As[k][ty * 4];
                float4 a1 = *(const float4*)&As[k][64 + ty * 4];
                float4 b0 = *(const float4*)&Bs[k][tx * 4];
                float4 b1 = *(const float4*)&Bs[k][64 + tx * 4];
                float a[8] = {a0.x, a0.y, a0.z, a0.w, a1.x, a1.y, a1.z, a1.w};
                float b[8] = {b0.x, b0.y, b0.z, b0.w, b1.x, b1.y, b1.z, b1.w};
#pragma unroll
                for (int i = 0; i < 8; i++)
#pragma unroll
                    for (int j = 0; j < 8; j++)
                        acc[i][j] = fmaf(a[i], b[j], acc[i][j]);
            }
            __syncthreads();
        }
        // fold relu(x2)*Wl3 into per-row partials
#pragma unroll
        for (int i = 0; i < 8; i++) {
#pragma unroll
            for (int j = 0; j < 8; j++) {
                const int gn = n0 + ((j < 4) ? (tx * 4 + j) : (64 + tx * 4 + j - 4));
                const float v = fmaxf(acc[i][j] + bl2s[gn], 0.f);
                padj[i] = fmaf(v, wl3s[gn], padj[i]);
            }
        }
    }

    // reduce over the 16 tx lanes (contiguous lanes within each half-warp)
    const float b3 = bl3[0];
#pragma unroll
    for (int i = 0; i < 8; i++) {
        float s = padj[i];
#pragma unroll
        for (int o = 8; o > 0; o >>= 1) s += __shfl_xor_sync(0xffffffffu, s, o);
        if (tx == 0) {
            const int gm = m0 + ((i < 4) ? (ty * 4 + i) : (64 + ty * 4 + i - 4));
            const float v = s + b3;
            adj[gm] = v;
            sig[gm] = sigmoidf(v);
        }
    }
}

// ---------------- message kernel ----------------
// For block (coltile, i, b): over all 128 sources w, compute
//   M[b,i,w,d] = relu([h[b,w,:], ef[b,i,w,:]] @ Wm^T + bm) * sig[b,i,w]
// write transposed into es[b,w,i,d], and reduce over w into msum[b,i,d].
__global__ __launch_bounds__(256, 2)
void msg_kernel(const float* __restrict__ h, const float* __restrict__ ef,
                const float* __restrict__ Wm, const float* __restrict__ bm,
                const float* __restrict__ sig,
                float* __restrict__ es, float* __restrict__ msum)
{
    __shared__ float As[16][132];
    __shared__ float Bs[16][68];
    __shared__ float sig_s[128];
    __shared__ float red[16][68];
    const int tid = threadIdx.x;
    const int b = blockIdx.z;
    const int ti = blockIdx.y;            // target node i
    const int n0 = blockIdx.x * 64;       // output feature tile
    const int tx = tid & 15, ty = tid >> 4;
    const int lr = tid >> 2, lk = (tid & 3) * 4;

    if (tid < 128) sig_s[tid] = sig[(size_t)(b * PN + ti) * PN + tid];

    float acc[8][4];
#pragma unroll
    for (int i = 0; i < 8; i++)
#pragma unroll
        for (int j = 0; j < 4; j++) acc[i][j] = 0.f;

    for (int kt = 0; kt < 2 * PD; kt += 16) {
#pragma unroll
        for (int half = 0; half < 2; half++) {
            const int w = lr + half * 64;
            const float* p = (kt < PD)
                ? (h + (size_t)(b * PN + w) * PD + kt + lk)
                : (ef + ((size_t)(b * PN + ti) * PN + w) * PD + (kt - PD) + lk);
            float4 v = *(const float4*)p;
            As[lk + 0][w] = v.x; As[lk + 1][w] = v.y;
            As[lk + 2][w] = v.z; As[lk + 3][w] = v.w;
        }
        {
            const int d = lr;  // 0..63
            float4 v = *(const float4*)(Wm + (size_t)(n0 + d) * (2 * PD) + kt + lk);
            Bs[lk + 0][d] = v.x; Bs[lk + 1][d] = v.y;
            Bs[lk + 2][d] = v.z; Bs[lk + 3][d] = v.w;
        }
        __syncthreads();
#pragma unroll
        for (int k = 0; k < 16; k++) {
            float4 a0 = *(const float4*)&As[k][ty * 4];
            float4 a1 = *(const float4*)&As[k][64 + ty * 4];
            float4 b0 = *(const float4*)&Bs[k][tx * 4];
            float a[8] = {a0.x, a0.y, a0.z, a0.w, a1.x, a1.y, a1.z, a1.w};
            float bv[4] = {b0.x, b0.y, b0.z, b0.w};
#pragma unroll
            for (int i = 0; i < 8; i++)
#pragma unroll
                for (int j = 0; j < 4; j++)
                    acc[i][j] = fmaf(a[i], bv[j], acc[i][j]);
        }
        __syncthreads();
    }

    const float bm0 = bm[n0 + tx * 4 + 0];
    const float bm1 = bm[n0 + tx * 4 + 1];
    const float bm2 = bm[n0 + tx * 4 + 2];
    const float bm3 = bm[n0 + tx * 4 + 3];
    float csum[4] = {0.f, 0.f, 0.f, 0.f};
#pragma unroll
    for (int ii = 0; ii < 8; ii++) {
        const int w = (ii < 4) ? (ty * 4 + ii) : (64 + ty * 4 + ii - 4);
        const float sg = sig_s[w];
        float4 v;
        v.x = fmaxf(acc[ii][0] + bm0, 0.f) * sg;
        v.y = fmaxf(acc[ii][1] + bm1, 0.f) * sg;
        v.z = fmaxf(acc[ii][2] + bm2, 0.f) * sg;
        v.w = fmaxf(acc[ii][3] + bm3, 0.f) * sg;
        // transposed write: es[b, w, i, d]
        *(float4*)(es + ((size_t)(b * PN + w) * PN + ti) * PD + n0 + tx * 4) = v;
        csum[0] += v.x; csum[1] += v.y; csum[2] += v.z; csum[3] += v.w;
    }
    red[ty][tx * 4 + 0] = csum[0];
    red[ty][tx * 4 + 1] = csum[1];
    red[ty][tx * 4 + 2] = csum[2];
    red[ty][tx * 4 + 3] = csum[3];
    __syncthreads();
    if (tid < 64) {
        float s = 0.f;
#pragma unroll
        for (int t = 0; t < 16; t++) s += red[t][tid];
        msum[(size_t)(b * PN + ti) * PD + n0 + tid] = s;   // block exclusively owns this slice
    }
}

// ---------------- GRU elementwise update ----------------
__global__ void gru_kernel(const float* __restrict__ gi, const float* __restrict__ gh,
                           float* __restrict__ h)
{
    const int row = blockIdx.x;     // 0..1023
    const int d = threadIdx.x;      // 0..255
    const float* gir = gi + (size_t)row * 3 * PD;
    const float* ghr = gh + (size_t)row * 3 * PD;
    const float r = sigmoidf(gir[d] + ghr[d]);
    const float z = sigmoidf(gir[PD + d] + ghr[PD + d]);
    const float n = tanhf(gir[2 * PD + d] + r * ghr[2 * PD + d]);
    const size_t hi = (size_t)row * PD + d;
    h[hi] = (1.f - z) * n + z * h[hi];
}

// ---------------- launch ----------------
extern "C" void kernel_launch(void* const* d_in, const int* in_sizes, int n_in,
                              void* d_out, int out_size)
{
    const float* edge = (const float*)d_in[0];
    const float* node = (const float*)d_in[1];
    const float* W_er = (const float*)d_in[2];  const float* b_er = (const float*)d_in[3];
    const float* W_nr = (const float*)d_in[4];  const float* b_nr = (const float*)d_in[5];
    const float* Wl1  = (const float*)d_in[6];  const float* bl1  = (const float*)d_in[7];
    const float* Wl2  = (const float*)d_in[8];  const float* bl2  = (const float*)d_in[9];
    const float* Wl3  = (const float*)d_in[10]; const float* bl3  = (const float*)d_in[11];
    const float* W_m  = (const float*)d_in[12]; const float* b_m  = (const float*)d_in[13];
    const float* W_ih = (const float*)d_in[14]; const float* b_ih = (const float*)d_in[15];
    const float* W_hh = (const float*)d_in[16]; const float* b_hh = (const float*)d_in[17];
    const float* W_r  = (const float*)d_in[18]; const float* b_r  = (const float*)d_in[19];
    float* out = (float*)d_out;

    float *ef, *es, *x1, *h, *sg, *ms, *gi, *gh;
    cudaGetSymbolAddress((void**)&ef, g_ef);
    cudaGetSymbolAddress((void**)&es, g_es);
    cudaGetSymbolAddress((void**)&x1, g_x1);
    cudaGetSymbolAddress((void**)&h,  g_h);
    cudaGetSymbolAddress((void**)&sg, g_sig);
    cudaGetSymbolAddress((void**)&ms, g_msum);
    cudaGetSymbolAddress((void**)&gi, g_gi);
    cudaGetSymbolAddress((void**)&gh, g_gh);

    const dim3 blk(256);
    auto gemm = [&](const float* A, const float* B, const float* bias, float* C,
                    int M, int N, int K, int relu) {
        dim3 grid((N + 127) / 128, (M + 127) / 128);
        sgemm_tn<<<grid, blk>>>(A, B, bias, C, M, N, K, relu);
    };

    // feature resize
    gemm(edge, W_er, b_er, ef, M_EDGE, PD, 200, 0);
    gemm(node, W_nr, b_nr, h, PB * PN, PD, 100, 0);

    for (int p = 0; p < 3; p++) {
        const float* esin = (p == 0) ? ef : es;
        // link function (per-edge MLP): layer1 GEMM, then fused layer2+3
        gemm(esin, Wl1, bl1, x1, M_EDGE, PLH, PD, 1);
        link23_kernel<<<M_EDGE / 128, blk>>>(x1, Wl2, bl2, Wl3, bl3, out, sg);
        // messages + gating + transpose + aggregate
        {
            dim3 mg(PD / 64, PN, PB);
            msg_kernel<<<mg, blk>>>(h, ef, W_m, b_m, sg, es, ms);
        }
        // GRU
        gemm(ms, W_ih, b_ih, gi, PB * PN, 3 * PD, PD, 0);
        gemm(h,  W_hh, b_hh, gh, PB * PN, 3 * PD, PD, 0);
        gru_kernel<<<PB * PN, PD>>>(gi, gh, h);
    }

    // readout
    gemm(h, W_r, b_r, out + M_EDGE, PB * PN, PC, PD, 0);
}

// round 9
// speedup vs baseline: 1.9555x; 1.9555x over previous
#include <cuda_runtime.h>
#include <math.h>
#include <stdint.h>

// Problem constants
#define PB 8
#define PN 128
#define PD 256
#define PLH 512
#define PC 117
#define M_EDGE (PB*PN*PN)   // 131072

// ---------------- scratch (static device globals; no allocation) ----------------
__device__ float g_ef[(size_t)M_EDGE * PD];
__device__ float g_es[(size_t)M_EDGE * PD];
__device__ float g_x1[(size_t)M_EDGE * PLH];
__device__ float g_h[PB * PN * PD];
__device__ float g_sig[M_EDGE];
__device__ float g_padjp[4 * (size_t)M_EDGE];
__device__ float g_msum[PB * PN * PD];
__device__ float g_hm[PB * PN * PD];
__device__ float g_gi[PB * PN * 3 * PD];
__device__ float g_gh[PB * PN * 3 * PD];

__device__ __forceinline__ float sigmoidf(float x) { return 1.f / (1.f + __expf(-x)); }

// ================= tf32 mma.sync building blocks =================
// smem layout: S[k][row], row-stride 132. Fragment LDS is bank-conflict-free.

__device__ __forceinline__ void ld_tile(float (*S)[132], const float* __restrict__ G,
                                        int ld, int kt, int K)
{
#pragma unroll
    for (int it = 0; it < 4; it++) {
        const int idx = threadIdx.x + it * 256;       // 1024 float4s total
        const int row = idx >> 3;
        const int c4 = (idx & 7) << 2;
        const int gk = kt + c4;
        float4 v = make_float4(0.f, 0.f, 0.f, 0.f);
        const float* p = G + (size_t)row * ld + gk;
        if (gk + 4 <= K) v = *(const float4*)p;
        else {
            if (gk + 0 < K) v.x = p[0];
            if (gk + 1 < K) v.y = p[1];
            if (gk + 2 < K) v.z = p[2];
            if (gk + 3 < K) v.w = p[3];
        }
        uint32_t t0, t1, t2, t3;
        asm("cvt.rna.tf32.f32 %0, %1;" : "=r"(t0) : "f"(v.x));
        asm("cvt.rna.tf32.f32 %0, %1;" : "=r"(t1) : "f"(v.y));
        asm("cvt.rna.tf32.f32 %0, %1;" : "=r"(t2) : "f"(v.z));
        asm("cvt.rna.tf32.f32 %0, %1;" : "=r"(t3) : "f"(v.w));
        S[c4 + 0][row] = __uint_as_float(t0);
        S[c4 + 1][row] = __uint_as_float(t1);
        S[c4 + 2][row] = __uint_as_float(t2);
        S[c4 + 3][row] = __uint_as_float(t3);
    }
}

// one 32-wide K chunk of the 128x128 block tile (warp = 64x32 tile)
__device__ __forceinline__ void mma_chunk(float acc[4][4][4],
                                          const float (*As)[132], const float (*Bs)[132],
                                          int wm, int wn, int g, int t)
{
#pragma unroll
    for (int k8 = 0; k8 < 32; k8 += 8) {
        uint32_t af[4][4], bf[4][2];
#pragma unroll
        for (int mf = 0; mf < 4; mf++) {
            const int rb = wm * 64 + mf * 16;
            af[mf][0] = __float_as_uint(As[k8 + t][rb + g]);
            af[mf][1] = __float_as_uint(As[k8 + t][rb + 8 + g]);
            af[mf][2] = __float_as_uint(As[k8 + 4 + t][rb + g]);
            af[mf][3] = __float_as_uint(As[k8 + 4 + t][rb + 8 + g]);
        }
#pragma unroll
        for (int nf = 0; nf < 4; nf++) {
            const int cb = wn * 32 + nf * 8;
            bf[nf][0] = __float_as_uint(Bs[k8 + t][cb + g]);
            bf[nf][1] = __float_as_uint(Bs[k8 + 4 + t][cb + g]);
        }
#pragma unroll
        for (int mf = 0; mf < 4; mf++)
#pragma unroll
            for (int nf = 0; nf < 4; nf++)
                asm volatile(
                    "mma.sync.aligned.m16n8k8.row.col.f32.tf32.tf32.f32 "
                    "{%0,%1,%2,%3}, {%4,%5,%6,%7}, {%8,%9}, {%0,%1,%2,%3};"
                    : "+f"(acc[mf][nf][0]), "+f"(acc[mf][nf][1]),
                      "+f"(acc[mf][nf][2]), "+f"(acc[mf][nf][3])
                    : "r"(af[mf][0]), "r"(af[mf][1]), "r"(af[mf][2]), "r"(af[mf][3]),
                      "r"(bf[nf][0]), "r"(bf[nf][1]));
    }
}

// ---------------- generic tf32 GEMM: C = act(A@B^T + bias) ----------------
// grid: (N/128, M/128). M,N multiples of 128.
__global__ __launch_bounds__(256, 2)
void mgemm(const float* __restrict__ A, int lda, const float* __restrict__ B, int ldb,
           int K, const float* __restrict__ bias, int relu,
           float* __restrict__ C, int ldc)
{
    __shared__ float As[32][132];
    __shared__ float Bs[32][132];
    const int tid = threadIdx.x, lane = tid & 31, wid = tid >> 5;
    const int wm = wid >> 2, wn = wid & 3, g = lane >> 2, t = lane & 3;
    const int m0 = blockIdx.y * 128, n0 = blockIdx.x * 128;
    const float* Ab = A + (size_t)m0 * lda;
    const float* Bb = B + (size_t)n0 * ldb;

    float acc[4][4][4];
#pragma unroll
    for (int a = 0; a < 4; a++)
#pragma unroll
        for (int b = 0; b < 4; b++)
#pragma unroll
            for (int c = 0; c < 4; c++) acc[a][b][c] = 0.f;

    for (int kt = 0; kt < K; kt += 32) {
        ld_tile(As, Ab, lda, kt, K);
        ld_tile(Bs, Bb, ldb, kt, K);
        __syncthreads();
        mma_chunk(acc, As, Bs, wm, wn, g, t);
        __syncthreads();
    }

#pragma unroll
    for (int mf = 0; mf < 4; mf++) {
        const int r0 = m0 + wm * 64 + mf * 16 + g;
#pragma unroll
        for (int nf = 0; nf < 4; nf++) {
            const int c = n0 + wn * 32 + nf * 8 + t * 2;
            const float b0 = bias[c], b1 = bias[c + 1];
            float2 v0 = make_float2(acc[mf][nf][0] + b0, acc[mf][nf][1] + b1);
            float2 v1 = make_float2(acc[mf][nf][2] + b0, acc[mf][nf][3] + b1);
            if (relu) {
                v0.x = fmaxf(v0.x, 0.f); v0.y = fmaxf(v0.y, 0.f);
                v1.x = fmaxf(v1.x, 0.f); v1.y = fmaxf(v1.y, 0.f);
            }
            *(float2*)&C[(size_t)r0 * ldc + c] = v0;
            *(float2*)&C[(size_t)(r0 + 8) * ldc + c] = v1;
        }
    }
}

// ---------------- fused link layer2+3: per-row partial adjacency ----------------
// grid: (4, M_EDGE/128). padjp[nt*M + m] = sum_{n in tile nt} relu(x1@Wl2^T + bl2)*wl3
__global__ __launch_bounds__(256, 2)
void link23_mma(const float* __restrict__ x1, const float* __restrict__ Wl2,
                const float* __restrict__ bl2, const float* __restrict__ wl3,
                float* __restrict__ padjp)
{
    __shared__ float As[32][132];
    __shared__ float Bs[32][132];
    __shared__ float wred[4][128];
    const int tid = threadIdx.x, lane = tid & 31, wid = tid >> 5;
    const int wm = wid >> 2, wn = wid & 3, g = lane >> 2, t = lane & 3;
    const int nt = blockIdx.x;
    const int m0 = blockIdx.y * 128;
    const int n0 = nt * 128;
    const float* Ab = x1 + (size_t)m0 * PLH;
    const float* Bb = Wl2 + (size_t)n0 * PLH;

    float acc[4][4][4];
#pragma unroll
    for (int a = 0; a < 4; a++)
#pragma unroll
        for (int b = 0; b < 4; b++)
#pragma unroll
            for (int c = 0; c < 4; c++) acc[a][b][c] = 0.f;

    for (int kt = 0; kt < PLH; kt += 32) {
        ld_tile(As, Ab, PLH, kt, PLH);
        ld_tile(Bs, Bb, PLH, kt, PLH);
        __syncthreads();
        mma_chunk(acc, As, Bs, wm, wn, g, t);
        __syncthreads();
    }

#pragma unroll
    for (int mf = 0; mf < 4; mf++) {
        float s0 = 0.f, s1 = 0.f;
#pragma unroll
        for (int nf = 0; nf < 4; nf++) {
            const int c = n0 + wn * 32 + nf * 8 + t * 2;
            const float bb0 = bl2[c], bb1 = bl2[c + 1];
            const float w0 = wl3[c], w1 = wl3[c + 1];
            s0 = fmaf(fmaxf(acc[mf][nf][0] + bb0, 0.f), w0, s0);
            s0 = fmaf(fmaxf(acc[mf][nf][1] + bb1, 0.f), w1, s0);
            s1 = fmaf(fmaxf(acc[mf][nf][2] + bb0, 0.f), w0, s1);
            s1 = fmaf(fmaxf(acc[mf][nf][3] + bb1, 0.f), w1, s1);
        }
        // reduce over the 4-lane column subgroup (t)
        s0 += __shfl_xor_sync(0xffffffffu, s0, 1);
        s0 += __shfl_xor_sync(0xffffffffu, s0, 2);
        s1 += __shfl_xor_sync(0xffffffffu, s1, 1);
        s1 += __shfl_xor_sync(0xffffffffu, s1, 2);
        if (t == 0) {
            wred[wn][wm * 64 + mf * 16 + g] = s0;
            wred[wn][wm * 64 + mf * 16 + 8 + g] = s1;
        }
    }
    __syncthreads();
    if (tid < 128)
        padjp[(size_t)nt * M_EDGE + m0 + tid] =
            wred[0][tid] + wred[1][tid] + wred[2][tid] + wred[3][tid];
}

// ---------------- message kernel ----------------
// grid: (2, PN, PB). For block (nt, i, b): D = ef[b,i] @ WmR^T (K=256),
// v = relu(D + hm[b,w,:]) * sig[b,i,w]; es[b,w,i,:] = v; msum[b,i,:] = sum_w v.
__global__ __launch_bounds__(256, 2)
void msg_mma(const float* __restrict__ ef, const float* __restrict__ WmR,
             const float* __restrict__ hm, const float* __restrict__ sig,
             float* __restrict__ es, float* __restrict__ msum)
{
    __shared__ float As[32][132];
    __shared__ float Bs[32][132];
    __shared__ float cred[2][128];
    const int tid = threadIdx.x, lane = tid & 31, wid = tid >> 5;
    const int wm = wid >> 2, wn = wid & 3, g = lane >> 2, t = lane & 3;
    const int n0 = blockIdx.x * 128;
    const int i = blockIdx.y, b = blockIdx.z;
    const float* Ab = ef + ((size_t)(b * PN + i) * PN) * PD;
    const float* Bb = WmR + (size_t)n0 * (2 * PD);
    const float* hmB = hm + (size_t)b * PN * PD;
    const float* sgB = sig + (size_t)(b * PN + i) * PN;

    float acc[4][4][4];
#pragma unroll
    for (int a = 0; a < 4; a++)
#pragma unroll
        for (int bb = 0; bb < 4; bb++)
#pragma unroll
            for (int c = 0; c < 4; c++) acc[a][bb][c] = 0.f;

    for (int kt = 0; kt < PD; kt += 32) {
        ld_tile(As, Ab, PD, kt, PD);
        ld_tile(Bs, Bb, 2 * PD, kt, PD);
        __syncthreads();
        mma_chunk(acc, As, Bs, wm, wn, g, t);
        __syncthreads();
    }

    float psum[4][2];
#pragma unroll
    for (int nf = 0; nf < 4; nf++) { psum[nf][0] = 0.f; psum[nf][1] = 0.f; }

#pragma unroll
    for (int mf = 0; mf < 4; mf++) {
        const int w0 = wm * 64 + mf * 16 + g;
        const int w1 = w0 + 8;
        const float sg0 = sgB[w0], sg1 = sgB[w1];
#pragma unroll
        for (int nf = 0; nf < 4; nf++) {
            const int d = n0 + wn * 32 + nf * 8 + t * 2;
            const float2 h0 = *(const float2*)&hmB[(size_t)w0 * PD + d];
            const float2 h1 = *(const float2*)&hmB[(size_t)w1 * PD + d];
            float2 v0, v1;
            v0.x = fmaxf(acc[mf][nf][0] + h0.x, 0.f) * sg0;
            v0.y = fmaxf(acc[mf][nf][1] + h0.y, 0.f) * sg0;
            v1.x = fmaxf(acc[mf][nf][2] + h1.x, 0.f) * sg1;
            v1.y = fmaxf(acc[mf][nf][3] + h1.y, 0.f) * sg1;
            *(float2*)&es[((size_t)(b * PN + w0) * PN + i) * PD + d] = v0;
            *(float2*)&es[((size_t)(b * PN + w1) * PN + i) * PD + d] = v1;
            psum[nf][0] += v0.x + v1.x;
            psum[nf][1] += v0.y + v1.y;
        }
    }
    // reduce over rows within warp (lanes sharing same t): xor 4,8,16
#pragma unroll
    for (int nf = 0; nf < 4; nf++) {
#pragma unroll
        for (int q = 0; q < 2; q++) {
            float s = psum[nf][q];
            s += __shfl_xor_sync(0xffffffffu, s, 4);
            s += __shfl_xor_sync(0xffffffffu, s, 8);
            s += __shfl_xor_sync(0xffffffffu, s, 16);
            if (g == 0) cred[wm][wn * 32 + nf * 8 + t * 2 + q] = s;
        }
    }
    __syncthreads();
    if (tid < 128)
        msum[(size_t)(b * PN + i) * PD + n0 + tid] = cred[0][tid] + cred[1][tid];
}

// ---------------- SIMT SGEMM (small matrices): C = act(A@B^T + bias) ----------------
__global__ __launch_bounds__(256, 2)
void sgemm_tn(const float* __restrict__ A, int lda, const float* __restrict__ B, int ldb,
              const float* __restrict__ bias, float* __restrict__ C, int ldc,
              int M, int N, int K, int relu)
{
    __shared__ float As[16][132];
    __shared__ float Bs[16][132];
    const int tid = threadIdx.x;
    const int m0 = blockIdx.y * 128;
    const int n0 = blockIdx.x * 128;
    const int lr = tid >> 2;
    const int lk = (tid & 3) * 4;
    const int tx = tid & 15;
    const int ty = tid >> 4;

    float acc[8][8];
#pragma unroll
    for (int i = 0; i < 8; i++)
#pragma unroll
        for (int j = 0; j < 8; j++) acc[i][j] = 0.f;

    for (int kt = 0; kt < K; kt += 16) {
        const bool fullk = (kt + 16 <= K);
#pragma unroll
        for (int half = 0; half < 2; half++) {
            const int row = lr + half * 64;
            {
                const int gm = m0 + row;
                float4 v = make_float4(0.f, 0.f, 0.f, 0.f);
                if (gm < M) {
                    const float* p = A + (size_t)gm * lda + kt + lk;
                    if (fullk) v = *(const float4*)p;
                    else {
                        if (kt + lk + 0 < K) v.x = p[0];
                        if (kt + lk + 1 < K) v.y = p[1];
                        if (kt + lk + 2 < K) v.z = p[2];
                        if (kt + lk + 3 < K) v.w = p[3];
                    }
                }
                As[lk + 0][row] = v.x; As[lk + 1][row] = v.y;
                As[lk + 2][row] = v.z; As[lk + 3][row] = v.w;
            }
            {
                const int gn = n0 + row;
                float4 v = make_float4(0.f, 0.f, 0.f, 0.f);
                if (gn < N) {
                    const float* p = B + (size_t)gn * ldb + kt + lk;
                    if (fullk) v = *(const float4*)p;
                    else {
                        if (kt + lk + 0 < K) v.x = p[0];
                        if (kt + lk + 1 < K) v.y = p[1];
                        if (kt + lk + 2 < K) v.z = p[2];
                        if (kt + lk + 3 < K) v.w = p[3];
                    }
                }
                Bs[lk + 0][row] = v.x; Bs[lk + 1][row] = v.y;
                Bs[lk + 2][row] = v.z; Bs[lk + 3][row] = v.w;
            }
        }
        __syncthreads();
#pragma unroll
        for (int k = 0; k < 16; k++) {
            float4 a0 = *(const float4*)&As[k][ty * 4];
            float4 a1 = *(const float4*)&As[k][64 + ty * 4];
            float4 b0 = *(const float4*)&Bs[k][tx * 4];
            float4 b1 = *(const float4*)&Bs[k][64 + tx * 4];
            float a[8] = {a0.x, a0.y, a0.z, a0.w, a1.x, a1.y, a1.z, a1.w};
            float b[8] = {b0.x, b0.y, b0.z, b0.w, b1.x, b1.y, b1.z, b1.w};
#pragma unroll
            for (int i = 0; i < 8; i++)
#pragma unroll
                for (int j = 0; j < 8; j++)
                    acc[i][j] = fmaf(a[i], b[j], acc[i][j]);
        }
        __syncthreads();
    }

#pragma unroll
    for (int i = 0; i < 8; i++) {
        const int gm = m0 + ((i < 4) ? (ty * 4 + i) : (64 + ty * 4 + i - 4));
        if (gm >= M) continue;
#pragma unroll
        for (int j = 0; j < 8; j++) {
            const int gn = n0 + ((j < 4) ? (tx * 4 + j) : (64 + tx * 4 + j - 4));
            if (gn >= N) continue;
            float v = acc[i][j] + bias[gn];
            if (relu) v = fmaxf(v, 0.f);
            C[(size_t)gm * ldc + gn] = v;
        }
    }
}

// ---------------- adjacency finalize ----------------
__global__ void adj_fin(const float* __restrict__ padjp, const float* __restrict__ bl3,
                        float* __restrict__ adj, float* __restrict__ sig)
{
    const int m = blockIdx.x * 256 + threadIdx.x;
    const float v = padjp[m] + padjp[M_EDGE + m] + padjp[2 * (size_t)M_EDGE + m]
                  + padjp[3 * (size_t)M_EDGE + m] + bl3[0];
    adj[m] = v;
    sig[m] = sigmoidf(v);
}

// ---------------- GRU elementwise update ----------------
__global__ void gru_kernel(const float* __restrict__ gi, const float* __restrict__ gh,
                           float* __restrict__ h)
{
    const int row = blockIdx.x;
    const int d = threadIdx.x;
    const float* gir = gi + (size_t)row * 3 * PD;
    const float* ghr = gh + (size_t)row * 3 * PD;
    const float r = sigmoidf(gir[d] + ghr[d]);
    const float z = sigmoidf(gir[PD + d] + ghr[PD + d]);
    const float n = tanhf(gir[2 * PD + d] + r * ghr[2 * PD + d]);
    const size_t hi = (size_t)row * PD + d;
    h[hi] = (1.f - z) * n + z * h[hi];
}

// ---------------- launch ----------------
extern "C" void kernel_launch(void* const* d_in, const int* in_sizes, int n_in,
                              void* d_out, int out_size)
{
    const float* edge = (const float*)d_in[0];
    const float* node = (const float*)d_in[1];
    const float* W_er = (const float*)d_in[2];  const float* b_er = (const float*)d_in[3];
    const float* W_nr = (const float*)d_in[4];  const float* b_nr = (const float*)d_in[5];
    const float* Wl1  = (const float*)d_in[6];  const float* bl1  = (const float*)d_in[7];
    const float* Wl2  = (const float*)d_in[8];  const float* bl2  = (const float*)d_in[9];
    const float* Wl3  = (const float*)d_in[10]; const float* bl3  = (const float*)d_in[11];
    const float* W_m  = (const float*)d_in[12]; const float* b_m  = (const float*)d_in[13];
    const float* W_ih = (const float*)d_in[14]; const float* b_ih = (const float*)d_in[15];
    const float* W_hh = (const float*)d_in[16]; const float* b_hh = (const float*)d_in[17];
    const float* W_r  = (const float*)d_in[18]; const float* b_r  = (const float*)d_in[19];
    float* out = (float*)d_out;

    float *ef, *es, *x1, *h, *sg, *padjp, *ms, *hm, *gi, *gh;
    cudaGetSymbolAddress((void**)&ef,    g_ef);
    cudaGetSymbolAddress((void**)&es,    g_es);
    cudaGetSymbolAddress((void**)&x1,    g_x1);
    cudaGetSymbolAddress((void**)&h,     g_h);
    cudaGetSymbolAddress((void**)&sg,    g_sig);
    cudaGetSymbolAddress((void**)&padjp, g_padjp);
    cudaGetSymbolAddress((void**)&ms,    g_msum);
    cudaGetSymbolAddress((void**)&hm,    g_hm);
    cudaGetSymbolAddress((void**)&gi,    g_gi);
    cudaGetSymbolAddress((void**)&gh,    g_gh);

    auto gemm = [&](const float* A, int lda, const float* B, int ldb, const float* bias,
                    float* C, int ldc, int M, int N, int K, int relu) {
        dim3 grid((N + 127) / 128, (M + 127) / 128);
        sgemm_tn<<<grid, 256>>>(A, lda, B, ldb, bias, C, ldc, M, N, K, relu);
    };

    // feature resize: edge (tensor path), node (SIMT)
    mgemm<<<dim3(2, M_EDGE / 128), 256>>>(edge, 200, W_er, 200, 200, b_er, 0, ef, PD);
    gemm(node, 100, W_nr, 100, b_nr, h, PD, PB * PN, PD, 100, 0);

    for (int p = 0; p < 3; p++) {
        const float* esin = (p == 0) ? ef : es;
        // link fn layer1 (relu) — tensor
        mgemm<<<dim3(4, M_EDGE / 128), 256>>>(esin, PD, Wl1, PD, PD, bl1, 1, x1, PLH);
        // link fn layer2+3 fused — tensor, deterministic 4-slice partials
        link23_mma<<<dim3(4, M_EDGE / 128), 256>>>(x1, Wl2, bl2, Wl3, padjp);
        adj_fin<<<M_EDGE / 256, 256>>>(padjp, bl3, out, sg);
        // Hm = h @ Wm[:, :256]^T + b_m (node part of message)
        gemm(h, PD, W_m, 2 * PD, b_m, hm, PD, PB * PN, PD, PD, 0);
        // messages: edge-part GEMM + fused epilogue — tensor
        msg_mma<<<dim3(2, PN, PB), 256>>>(ef, W_m + PD, hm, sg, es, ms);
        // GRU
        gemm(ms, PD, W_ih, PD, b_ih, gi, 3 * PD, PB * PN, 3 * PD, PD, 0);
        gemm(h,  PD, W_hh, PD, b_hh, gh, 3 * PD, PB * PN, 3 * PD, PD, 0);
        gru_kernel<<<PB * PN, PD>>>(gi, gh, h);
    }

    // readout
    gemm(h, PD, W_r, PD, b_r, out + M_EDGE, PC, PB * PN, PC, PD, 0);
}

// round 12
// speedup vs baseline: 2.9665x; 1.5170x over previous
#include <cuda_runtime.h>
#include <math.h>
#include <stdint.h>

// Problem constants
#define PB 8
#define PN 128
#define PD 256
#define PLH 512
#define PC 117
#define M_EDGE (PB*PN*PN)   // 131072

// Tensor GEMM tile config: block 128(M) x 256(N) x 32(K), 8 warps of 64x64
#define ASZ 4224            // A stage floats: 8 Rblk * 4 K8 * 132
#define BSZ 8448            // B stage floats: 16 Cblk * 4 K8 * 132
#define STG (ASZ + BSZ)     // 12672 floats per stage
#define TG_SMEM (2 * STG * 4)  // 101376 bytes (double buffered)

// ---------------- scratch (static device globals; no allocation) ----------------
__device__ float g_ef[(size_t)M_EDGE * PD];
__device__ float g_es[(size_t)M_EDGE * PD];
__device__ float g_x1[(size_t)M_EDGE * PLH];
__device__ float g_h[PB * PN * PD];
__device__ float g_sig[M_EDGE];
__device__ float g_padjp[2 * (size_t)M_EDGE];
__device__ float g_msum[PB * PN * PD];
__device__ float g_hm[PB * PN * PD];
__device__ float g_gi[PB * PN * 3 * PD];
__device__ float g_gh[PB * PN * 3 * PD];

__device__ __forceinline__ float sigmoidf(float x) { return 1.f / (1.f + __expf(-x)); }

__device__ __forceinline__ float to_tf32(float x) {
    uint32_t u;
    asm("cvt.rna.tf32.f32 %0, %1;" : "=r"(u) : "f"(x));
    return __uint_as_float(u);
}

// ================= tf32 mma.sync core =================
// Interleaved smem layout per 32-K chunk:
//   off(r,k) = (R*4 + K8)*132 + (g*4 + t)*4 + k1*2 + r1
//   where g=r&7, r1=(r>>3)&1, R=r>>4, t=k&3, k1=(k>>2)&1, K8=k>>3.
// Fragment load: float4 at (R*4+K8)*132 + lane*4 -> mma quad, conflict-free.

__device__ __forceinline__ void mma8(float acc[4], float4 a, float b0, float b1) {
    asm volatile(
        "mma.sync.aligned.m16n8k8.row.col.f32.tf32.tf32.f32 "
        "{%0,%1,%2,%3}, {%4,%5,%6,%7}, {%8,%9}, {%0,%1,%2,%3};"
        : "+f"(acc[0]), "+f"(acc[1]), "+f"(acc[2]), "+f"(acc[3])
        : "r"(__float_as_uint(a.x)), "r"(__float_as_uint(a.y)),
          "r"(__float_as_uint(a.z)), "r"(__float_as_uint(a.w)),
          "r"(__float_as_uint(b0)), "r"(__float_as_uint(b1)));
}

// prefetch a ROWSx32 fp32 tile into registers (NV float4 per thread)
template<int NV>
__device__ __forceinline__ void ldg_tile(float4* v, const float* __restrict__ G,
                                         int ld, int kt, int K)
{
#pragma unroll
    for (int i = 0; i < NV; i++) {
        const int idx = threadIdx.x + i * 256;
        const int r = idx >> 3, kq = idx & 7;
        const int gk = kt + kq * 4;
        float4 t = make_float4(0.f, 0.f, 0.f, 0.f);
        if (gk < K) t = *(const float4*)(G + (size_t)r * ld + gk);  // K always %4==0
        v[i] = t;
    }
}

// store prefetched tile into interleaved smem layout (with tf32 rounding)
template<int NV>
__device__ __forceinline__ void sts_tile(float* S, const float4* v)
{
#pragma unroll
    for (int i = 0; i < NV; i++) {
        const int idx = threadIdx.x + i * 256;
        const int r = idx >> 3, kq = idx & 7;
        const int base = ((r >> 4) * 4 + (kq >> 1)) * 132 + (r & 7) * 16
                       + (kq & 1) * 2 + ((r >> 3) & 1);
        S[base + 0]  = to_tf32(v[i].x);
        S[base + 4]  = to_tf32(v[i].y);
        S[base + 8]  = to_tf32(v[i].z);
        S[base + 12] = to_tf32(v[i].w);
    }
}

// one 32-K chunk of mma over the 128x256 block (warp = 64x64)
__device__ __forceinline__ void mma_buf(const float* As, const float* Bs,
                                        float acc[4][8][4], int wm, int wn, int lane)
{
#pragma unroll
    for (int K8 = 0; K8 < 4; K8++) {
        float4 av[4];
#pragma unroll
        for (int mf = 0; mf < 4; mf++)
            av[mf] = *(const float4*)(As + ((wm * 4 + mf) * 4 + K8) * 132 + lane * 4);
#pragma unroll
        for (int np = 0; np < 4; np++) {
            const float4 bv = *(const float4*)(Bs + ((wn * 4 + np) * 4 + K8) * 132 + lane * 4);
#pragma unroll
            for (int mf = 0; mf < 4; mf++) {
                mma8(acc[mf][2 * np],     av[mf], bv.x, bv.z);
                mma8(acc[mf][2 * np + 1], av[mf], bv.y, bv.w);
            }
        }
    }
}

// shared mainloop: fills acc for block (m0 rows x n0..n0+255 cols)
#define TG_MAINLOOP(Ab, lda, Bb, ldb, K)                                        \
    float* S0 = smem; float* S1 = smem + STG;                                   \
    float4 pa[4], pb[8];                                                        \
    float acc[4][8][4];                                                         \
    _Pragma("unroll") for (int a_ = 0; a_ < 4; a_++)                            \
    _Pragma("unroll") for (int b_ = 0; b_ < 8; b_++)                            \
    _Pragma("unroll") for (int c_ = 0; c_ < 4; c_++) acc[a_][b_][c_] = 0.f;     \
    ldg_tile<4>(pa, (Ab), (lda), 0, (K));                                       \
    ldg_tile<8>(pb, (Bb), (ldb), 0, (K));                                       \
    sts_tile<4>(S0, pa); sts_tile<8>(S0 + ASZ, pb);                             \
    __syncthreads();                                                            \
    const int CH = ((K) + 31) / 32;                                             \
    for (int c = 0; c < CH; c++) {                                              \
        float* Sc = (c & 1) ? S1 : S0;                                          \
        float* Sn = (c & 1) ? S0 : S1;                                          \
        if (c + 1 < CH) {                                                       \
            ldg_tile<4>(pa, (Ab), (lda), (c + 1) * 32, (K));                    \
            ldg_tile<8>(pb, (Bb), (ldb), (c + 1) * 32, (K));                    \
        }                                                                       \
        mma_buf(Sc, Sc + ASZ, acc, wm, wn, lane);                               \
        __syncthreads();                                                        \
        if (c + 1 < CH) {                                                       \
            sts_tile<4>(Sn, pa); sts_tile<8>(Sn + ASZ, pb);                     \
            __syncthreads();                                                    \
        }                                                                       \
    }

// ---------------- generic tensor GEMM: C = act(A@B^T + bias) ----------------
// grid: (N/256, M/128)
__global__ __launch_bounds__(256, 1)
void tgemm(const float* __restrict__ A, int lda, const float* __restrict__ B, int ldb,
           int K, const float* __restrict__ bias, int relu,
           float* __restrict__ C, int ldc)
{
    extern __shared__ float smem[];
    const int tid = threadIdx.x, lane = tid & 31, wid = tid >> 5;
    const int wm = wid >> 2, wn = wid & 3, g = lane >> 2, t = lane & 3;
    const int m0 = blockIdx.y * 128, n0 = blockIdx.x * 256;
    const float* Ab = A + (size_t)m0 * lda;
    const float* Bb = B + (size_t)n0 * ldb;

    TG_MAINLOOP(Ab, lda, Bb, ldb, K)

#pragma unroll
    for (int mf = 0; mf < 4; mf++) {
        const int r0 = m0 + wm * 64 + mf * 16 + g;
#pragma unroll
        for (int nf = 0; nf < 8; nf++) {
            const int c = n0 + wn * 64 + nf * 8 + t * 2;
            const float b0 = bias[c], b1 = bias[c + 1];
            float2 v0 = make_float2(acc[mf][nf][0] + b0, acc[mf][nf][1] + b1);
            float2 v1 = make_float2(acc[mf][nf][2] + b0, acc[mf][nf][3] + b1);
            if (relu) {
                v0.x = fmaxf(v0.x, 0.f); v0.y = fmaxf(v0.y, 0.f);
                v1.x = fmaxf(v1.x, 0.f); v1.y = fmaxf(v1.y, 0.f);
            }
            *(float2*)&C[(size_t)r0 * ldc + c] = v0;
            *(float2*)&C[(size_t)(r0 + 8) * ldc + c] = v1;
        }
    }
}

// ---------------- fused link layer2+3 ----------------
// grid: (2, M_EDGE/128). padjp[nt*M + m] = sum_{n in 256-tile nt} relu(x1@Wl2^T+bl2)*wl3
__global__ __launch_bounds__(256, 1)
void link23_t(const float* __restrict__ x1, const float* __restrict__ Wl2,
              const float* __restrict__ bl2, const float* __restrict__ wl3,
              float* __restrict__ padjp)
{
    extern __shared__ float smem[];
    const int tid = threadIdx.x, lane = tid & 31, wid = tid >> 5;
    const int wm = wid >> 2, wn = wid & 3, g = lane >> 2, t = lane & 3;
    const int nt = blockIdx.x;
    const int m0 = blockIdx.y * 128, n0 = nt * 256;
    const float* Ab = x1 + (size_t)m0 * PLH;
    const float* Bb = Wl2 + (size_t)n0 * PLH;

    TG_MAINLOOP(Ab, PLH, Bb, PLH, PLH)

    float* wred = smem;   // [4][128], smem free after final sync
#pragma unroll
    for (int mf = 0; mf < 4; mf++) {
        float s0 = 0.f, s1 = 0.f;
#pragma unroll
        for (int nf = 0; nf < 8; nf++) {
            const int c = n0 + wn * 64 + nf * 8 + t * 2;
            const float bb0 = bl2[c], bb1 = bl2[c + 1];
            const float w0 = wl3[c], w1 = wl3[c + 1];
            s0 = fmaf(fmaxf(acc[mf][nf][0] + bb0, 0.f), w0, s0);
            s0 = fmaf(fmaxf(acc[mf][nf][1] + bb1, 0.f), w1, s0);
            s1 = fmaf(fmaxf(acc[mf][nf][2] + bb0, 0.f), w0, s1);
            s1 = fmaf(fmaxf(acc[mf][nf][3] + bb1, 0.f), w1, s1);
        }
        s0 += __shfl_xor_sync(0xffffffffu, s0, 1);
        s0 += __shfl_xor_sync(0xffffffffu, s0, 2);
        s1 += __shfl_xor_sync(0xffffffffu, s1, 1);
        s1 += __shfl_xor_sync(0xffffffffu, s1, 2);
        if (t == 0) {
            wred[wn * 128 + wm * 64 + mf * 16 + g] = s0;
            wred[wn * 128 + wm * 64 + mf * 16 + 8 + g] = s1;
        }
    }
    __syncthreads();
    if (tid < 128)
        padjp[(size_t)nt * M_EDGE + m0 + tid] =
            wred[tid] + wred[128 + tid] + wred[256 + tid] + wred[384 + tid];
}

// ---------------- message kernel ----------------
// grid: (PN, PB). block (i, b): D = ef[b,i] @ WmR^T (128x256, K=256),
// v = relu(D + hm[b,w,:]) * sig[b,i,w]; es[b,w,i,:] = v; msum[b,i,:] = sum_w v.
__global__ __launch_bounds__(256, 1)
void msg_t(const float* __restrict__ ef, const float* __restrict__ WmR,
           const float* __restrict__ hm, const float* __restrict__ sig,
           float* __restrict__ es, float* __restrict__ msum)
{
    extern __shared__ float smem[];
    const int tid = threadIdx.x, lane = tid & 31, wid = tid >> 5;
    const int wm = wid >> 2, wn = wid & 3, g = lane >> 2, t = lane & 3;
    const int i = blockIdx.x, b = blockIdx.y;
    const float* Ab = ef + ((size_t)(b * PN + i) * PN) * PD;
    const float* hmB = hm + (size_t)b * PN * PD;
    const float* sgB = sig + (size_t)(b * PN + i) * PN;

    TG_MAINLOOP(Ab, PD, WmR, 2 * PD, PD)

    float psum[8][2];
#pragma unroll
    for (int nf = 0; nf < 8; nf++) { psum[nf][0] = 0.f; psum[nf][1] = 0.f; }

#pragma unroll
    for (int mf = 0; mf < 4; mf++) {
        const int w0 = wm * 64 + mf * 16 + g;
        const int w1 = w0 + 8;
        const float sg0 = sgB[w0], sg1 = sgB[w1];
#pragma unroll
        for (int nf = 0; nf < 8; nf++) {
            const int d = wn * 64 + nf * 8 + t * 2;
            const float2 h0 = *(const float2*)&hmB[(size_t)w0 * PD + d];
            const float2 h1 = *(const float2*)&hmB[(size_t)w1 * PD + d];
            float2 v0, v1;
            v0.x = fmaxf(acc[mf][nf][0] + h0.x, 0.f) * sg0;
            v0.y = fmaxf(acc[mf][nf][1] + h0.y, 0.f) * sg0;
            v1.x = fmaxf(acc[mf][nf][2] + h1.x, 0.f) * sg1;
            v1.y = fmaxf(acc[mf][nf][3] + h1.y, 0.f) * sg1;
            *(float2*)&es[((size_t)(b * PN + w0) * PN + i) * PD + d] = v0;
            *(float2*)&es[((size_t)(b * PN + w1) * PN + i) * PD + d] = v1;
            psum[nf][0] += v0.x + v1.x;
            psum[nf][1] += v0.y + v1.y;
        }
    }
    float* cred = smem;   // [2][256]
#pragma unroll
    for (int nf = 0; nf < 8; nf++) {
#pragma unroll
        for (int q = 0; q < 2; q++) {
            float s = psum[nf][q];
            s += __shfl_xor_sync(0xffffffffu, s, 4);
            s += __shfl_xor_sync(0xffffffffu, s, 8);
            s += __shfl_xor_sync(0xffffffffu, s, 16);
            if (g == 0) cred[wm * 256 + wn * 64 + nf * 8 + t * 2 + q] = s;
        }
    }
    __syncthreads();
    if (tid < 256)
        msum[(size_t)(b * PN + i) * PD + tid] = cred[tid] + cred[256 + tid];
}

// ---------------- SIMT SGEMM (fp32-exact path): C = act(A@B^T + bias) ----------------
__global__ __launch_bounds__(256, 2)
void sgemm_tn(const float* __restrict__ A, int lda, const float* __restrict__ B, int ldb,
              const float* __restrict__ bias, float* __restrict__ C, int ldc,
              int M, int N, int K, int relu)
{
    __shared__ float As[16][132];
    __shared__ float Bs[16][132];
    const int tid = threadIdx.x;
    const int m0 = blockIdx.y * 128;
    const int n0 = blockIdx.x * 128;
    const int lr = tid >> 2;
    const int lk = (tid & 3) * 4;
    const int tx = tid & 15;
    const int ty = tid >> 4;

    float acc[8][8];
#pragma unroll
    for (int i = 0; i < 8; i++)
#pragma unroll
        for (int j = 0; j < 8; j++) acc[i][j] = 0.f;

    for (int kt = 0; kt < K; kt += 16) {
        const bool fullk = (kt + 16 <= K);
#pragma unroll
        for (int half = 0; half < 2; half++) {
            const int row = lr + half * 64;
            {
                const int gm = m0 + row;
                float4 v = make_float4(0.f, 0.f, 0.f, 0.f);
                if (gm < M) {
                    const float* p = A + (size_t)gm * lda + kt + lk;
                    if (fullk) v = *(const float4*)p;
                    else {
                        if (kt + lk + 0 < K) v.x = p[0];
                        if (kt + lk + 1 < K) v.y = p[1];
                        if (kt + lk + 2 < K) v.z = p[2];
                        if (kt + lk + 3 < K) v.w = p[3];
                    }
                }
                As[lk + 0][row] = v.x; As[lk + 1][row] = v.y;
                As[lk + 2][row] = v.z; As[lk + 3][row] = v.w;
            }
            {
                const int gn = n0 + row;
                float4 v = make_float4(0.f, 0.f, 0.f, 0.f);
                if (gn < N) {
                    const float* p = B + (size_t)gn * ldb + kt + lk;
                    if (fullk) v = *(const float4*)p;
                    else {
                        if (kt + lk + 0 < K) v.x = p[0];
                        if (kt + lk + 1 < K) v.y = p[1];
                        if (kt + lk + 2 < K) v.z = p[2];
                        if (kt + lk + 3 < K) v.w = p[3];
                    }
                }
                Bs[lk + 0][row] = v.x; Bs[lk + 1][row] = v.y;
                Bs[lk + 2][row] = v.z; Bs[lk + 3][row] = v.w;
            }
        }
        __syncthreads();
#pragma unroll
        for (int k = 0; k < 16; k++) {
            float4 a0 = *(const float4*)&As[k][ty * 4];
            float4 a1 = *(const float4*)&As[k][64 + ty * 4];
            float4 b0 = *(const float4*)&Bs[k][tx * 4];
            float4 b1 = *(const float4*)&Bs[k][64 + tx * 4];
            float a[8] = {a0.x, a0.y, a0.z, a0.w, a1.x, a1.y, a1.z, a1.w};
            float b[8] = {b0.x, b0.y, b0.z, b0.w, b1.x, b1.y, b1.z, b1.w};
#pragma unroll
            for (int i = 0; i < 8; i++)
#pragma unroll
                for (int j = 0; j < 8; j++)
                    acc[i][j] = fmaf(a[i], b[j], acc[i][j]);
        }
        __syncthreads();
    }

#pragma unroll
    for (int i = 0; i < 8; i++) {
        const int gm = m0 + ((i < 4) ? (ty * 4 + i) : (64 + ty * 4 + i - 4));
        if (gm >= M) continue;
#pragma unroll
        for (int j = 0; j < 8; j++) {
            const int gn = n0 + ((j < 4) ? (tx * 4 + j) : (64 + tx * 4 + j - 4));
            if (gn >= N) continue;
            float v = acc[i][j] + bias[gn];
            if (relu) v = fmaxf(v, 0.f);
            C[(size_t)gm * ldc + gn] = v;
        }
    }
}

// ---------------- adjacency finalize ----------------
__global__ void adj_fin(const float* __restrict__ padjp, const float* __restrict__ bl3,
                        float* __restrict__ adj, float* __restrict__ sig)
{
    const int m = blockIdx.x * 256 + threadIdx.x;
    const float v = padjp[m] + padjp[M_EDGE + m] + bl3[0];
    adj[m] = v;
    sig[m] = sigmoidf(v);
}

// ---------------- GRU elementwise update ----------------
__global__ void gru_kernel(const float* __restrict__ gi, const float* __restrict__ gh,
                           float* __restrict__ h)
{
    const int row = blockIdx.x;
    const int d = threadIdx.x;
    const float* gir = gi + (size_t)row * 3 * PD;
    const float* ghr = gh + (size_t)row * 3 * PD;
    const float r = sigmoidf(gir[d] + ghr[d]);
    const float z = sigmoidf(gir[PD + d] + ghr[PD + d]);
    const float n = tanhf(gir[2 * PD + d] + r * ghr[2 * PD + d]);
    const size_t hi = (size_t)row * PD + d;
    h[hi] = (1.f - z) * n + z * h[hi];
}

// ---------------- launch ----------------
extern "C" void kernel_launch(void* const* d_in, const int* in_sizes, int n_in,
                              void* d_out, int out_size)
{
    const float* edge = (const float*)d_in[0];
    const float* node = (const float*)d_in[1];
    const float* W_er = (const float*)d_in[2];  const float* b_er = (const float*)d_in[3];
    const float* W_nr = (const float*)d_in[4];  const float* b_nr = (const float*)d_in[5];
    const float* Wl1  = (const float*)d_in[6];  const float* bl1  = (const float*)d_in[7];
    const float* Wl2  = (const float*)d_in[8];  const float* bl2  = (const float*)d_in[9];
    const float* Wl3  = (const float*)d_in[10]; const float* bl3  = (const float*)d_in[11];
    const float* W_m  = (const float*)d_in[12]; const float* b_m  = (const float*)d_in[13];
    const float* W_ih = (const float*)d_in[14]; const float* b_ih = (const float*)d_in[15];
    const float* W_hh = (const float*)d_in[16]; const float* b_hh = (const float*)d_in[17];
    const float* W_r  = (const float*)d_in[18]; const float* b_r  = (const float*)d_in[19];
    float* out = (float*)d_out;

    float *ef, *es, *x1, *h, *sg, *padjp, *ms, *hm, *gi, *gh;
    cudaGetSymbolAddress((void**)&ef,    g_ef);
    cudaGetSymbolAddress((void**)&es,    g_es);
    cudaGetSymbolAddress((void**)&x1,    g_x1);
    cudaGetSymbolAddress((void**)&h,     g_h);
    cudaGetSymbolAddress((void**)&sg,    g_sig);
    cudaGetSymbolAddress((void**)&padjp, g_padjp);
    cudaGetSymbolAddress((void**)&ms,    g_msum);
    cudaGetSymbolAddress((void**)&hm,    g_hm);
    cudaGetSymbolAddress((void**)&gi,    g_gi);
    cudaGetSymbolAddress((void**)&gh,    g_gh);

    cudaFuncSetAttribute(tgemm,    cudaFuncAttributeMaxDynamicSharedMemorySize, TG_SMEM);
    cudaFuncSetAttribute(link23_t, cudaFuncAttributeMaxDynamicSharedMemorySize, TG_SMEM);
    cudaFuncSetAttribute(msg_t,    cudaFuncAttributeMaxDynamicSharedMemorySize, TG_SMEM);

    auto tg = [&](const float* A, int lda, const float* B, int ldb, int K,
                  const float* bias, int relu, float* C, int ldc, int M, int N) {
        dim3 grid(N / 256, M / 128);
        tgemm<<<grid, 256, TG_SMEM>>>(A, lda, B, ldb, K, bias, relu, C, ldc);
    };
    auto sg32 = [&](const float* A, int lda, const float* B, int ldb, const float* bias,
                    float* C, int ldc, int M, int N, int K, int relu) {
        dim3 grid((N + 127) / 128, (M + 127) / 128);
        sgemm_tn<<<grid, 256>>>(A, lda, B, ldb, bias, C, ldc, M, N, K, relu);
    };

    // feature resize: edge (tensor), node (fp32 SIMT — feeds recurrent h path)
    tg(edge, 200, W_er, 200, 200, b_er, 0, ef, PD, M_EDGE, PD);
    sg32(node, 100, W_nr, 100, b_nr, h, PD, PB * PN, PD, 100, 0);

    for (int p = 0; p < 3; p++) {
        const float* esin = (p == 0) ? ef : es;
        // link fn layer1 (relu) — tensor
        tg(esin, PD, Wl1, PD, PD, bl1, 1, x1, PLH, M_EDGE, PLH);
        // link fn layer2+3 fused — tensor, deterministic 2-slice partials
        link23_t<<<dim3(2, M_EDGE / 128), 256, TG_SMEM>>>(x1, Wl2, bl2, Wl3, padjp);
        adj_fin<<<M_EDGE / 256, 256>>>(padjp, bl3, out, sg);
        // Hm = h @ Wm[:, :256]^T + b_m — fp32 SIMT (recurrent-path numerics)
        sg32(h, PD, W_m, 2 * PD, b_m, hm, PD, PB * PN, PD, PD, 0);
        // messages: edge-part GEMM + fused epilogue — tensor
        msg_t<<<dim3(PN, PB), 256, TG_SMEM>>>(ef, W_m + PD, hm, sg, es, ms);
        // GRU gates — fp32 SIMT (recurrent-path numerics)
        sg32(ms, PD, W_ih, PD, b_ih, gi, 3 * PD, PB * PN, 3 * PD, PD, 0);
        sg32(h,  PD, W_hh, PD, b_hh, gh, 3 * PD, PB * PN, 3 * PD, PD, 0);
        gru_kernel<<<PB * PN, PD>>>(gi, gh, h);
    }

    // readout (fp32 SIMT)
    sg32(h, PD, W_r, PD, b_r, out + M_EDGE, PC, PB * PN, PC, PD, 0);
}